// round 3
// baseline (speedup 1.0000x reference)
#include <cuda_runtime.h>
#include <math_constants.h>

#define NN 50000
#define EE 500000
#define SDIM 128
#define HID 64
#define DEPTH 4
#define FCUT 5.0f
#define MOUT 134            // SD + 2*VD
#define MPAD 160            // padded row for W3 in smem (conflict-free, safe c=4 column)

// ---------------- scratch (static device allocations, allowed) ----------------
__device__ float g_s[NN * SDIM];
__device__ float g_v[NN * 9];
__device__ float g_P[NN * 128];      // [n][0:64]=s@W1a (dst part), [64:128]=s@W1b (src part)
__device__ float g_sagg[NN * SDIM];
__device__ float g_vagg[NN * 9];
__device__ float g_C[EE];
__device__ float g_cnt[NN];
__device__ float g_invcnt[NN];

__device__ __forceinline__ float silu(float x) { return x / (1.0f + __expf(-x)); }

// ---------------- init kernels ----------------
__global__ void k_init(const float* __restrict__ s, const float* __restrict__ v)
{
    int idx = blockIdx.x * blockDim.x + threadIdx.x;
    if (idx < NN * SDIM) g_s[idx] = s[idx];
    if (idx < NN * 9)    g_v[idx] = v[idx];
    if (idx < NN)        g_cnt[idx] = 0.0f;
}

__global__ void k_edge_init(const int* __restrict__ ei, const float* __restrict__ dv)
{
    int e = blockIdx.x * blockDim.x + threadIdx.x;
    if (e >= EE) return;
    float dd = dv[e];
    float c = (dd < FCUT) ? 0.5f * (cosf(CUDART_PI_F * dd / FCUT) + 1.0f) : 0.0f;
    g_C[e] = c;
    atomicAdd(&g_cnt[ei[e]], 1.0f);   // ei row 0 = dst
}

__global__ void k_invcnt()
{
    int n = blockIdx.x * blockDim.x + threadIdx.x;
    if (n < NN) g_invcnt[n] = 1.0f / fmaxf(g_cnt[n], 1.0f);
}

// ---------------- node_pre: P = [s@W1a , s@W1b]; zero accumulators ----------------
__global__ __launch_bounds__(256) void k_node_pre(const float* __restrict__ W1, int layer)
{
    extern __shared__ float sm[];     // 128 x 128 combined weight block (64 KB)
    const float* W1l = W1 + (size_t)layer * 257 * 64;
    for (int i = threadIdx.x; i < 128 * 128; i += blockDim.x) {
        int k = i >> 7, j = i & 127;
        sm[i] = (j < 64) ? W1l[k * 64 + j] : W1l[(128 + k) * 64 + (j - 64)];
    }
    __syncthreads();

    const unsigned FULL = 0xffffffffu;
    int lane = threadIdx.x & 31;
    int gw = (blockIdx.x * blockDim.x + threadIdx.x) >> 5;
    int nw = (gridDim.x * blockDim.x) >> 5;

    for (int n0 = gw * 2; n0 < NN; n0 += nw * 2) {
        int n1 = n0 + 1;  // NN even
        float4 sa = ((const float4*)(g_s + (size_t)n0 * SDIM))[lane];
        float4 sb = ((const float4*)(g_s + (size_t)n1 * SDIM))[lane];
        float4 acc0 = make_float4(0.f, 0.f, 0.f, 0.f);
        float4 acc1 = make_float4(0.f, 0.f, 0.f, 0.f);
#pragma unroll 8
        for (int k4 = 0; k4 < 32; k4++) {
            float a0[4], a1[4];
            a0[0] = __shfl_sync(FULL, sa.x, k4); a0[1] = __shfl_sync(FULL, sa.y, k4);
            a0[2] = __shfl_sync(FULL, sa.z, k4); a0[3] = __shfl_sync(FULL, sa.w, k4);
            a1[0] = __shfl_sync(FULL, sb.x, k4); a1[1] = __shfl_sync(FULL, sb.y, k4);
            a1[2] = __shfl_sync(FULL, sb.z, k4); a1[3] = __shfl_sync(FULL, sb.w, k4);
#pragma unroll
            for (int c = 0; c < 4; c++) {
                const float4 w = *((const float4*)(sm + (((k4 << 2) + c) << 7) + (lane << 2)));
                acc0.x = fmaf(a0[c], w.x, acc0.x); acc0.y = fmaf(a0[c], w.y, acc0.y);
                acc0.z = fmaf(a0[c], w.z, acc0.z); acc0.w = fmaf(a0[c], w.w, acc0.w);
                acc1.x = fmaf(a1[c], w.x, acc1.x); acc1.y = fmaf(a1[c], w.y, acc1.y);
                acc1.z = fmaf(a1[c], w.z, acc1.z); acc1.w = fmaf(a1[c], w.w, acc1.w);
            }
        }
        ((float4*)(g_P + (size_t)n0 * 128))[lane] = acc0;
        ((float4*)(g_P + (size_t)n1 * 128))[lane] = acc1;
        float4 z = make_float4(0.f, 0.f, 0.f, 0.f);
        ((float4*)(g_sagg + (size_t)n0 * 128))[lane] = z;
        ((float4*)(g_sagg + (size_t)n1 * 128))[lane] = z;
        if (lane < 9) { g_vagg[n0 * 9 + lane] = 0.f; g_vagg[n1 * 9 + lane] = 0.f; }
    }
}

// ---------------- edge kernel: h1(from P) -> h2 -> m; scatter ms, vm ----------------
__global__ __launch_bounds__(256) void k_edge(
    const int* __restrict__ ei, const float* __restrict__ dv, const float* __restrict__ rv,
    const float* __restrict__ W1, const float* __restrict__ b1,
    const float* __restrict__ W2, const float* __restrict__ b2,
    const float* __restrict__ W3, const float* __restrict__ b3, int layer)
{
    extern __shared__ float sm[];
    float* W2s = sm;                       // 64*64
    float* W3s = W2s + 64 * 64;            // 64*MPAD
    float* w1ds = W3s + 64 * MPAD;         // 64 (d-row of W1)
    float* b1s = w1ds + 64;                // 64
    float* b2s = b1s + 64;                 // 64
    float* b3s = b2s + 64;                 // MPAD

    const float* W2l = W2 + (size_t)layer * 64 * 64;
    const float* W3l = W3 + (size_t)layer * 64 * MOUT;
    for (int i = threadIdx.x; i < 64 * 64; i += blockDim.x) W2s[i] = W2l[i];
    for (int i = threadIdx.x; i < 64 * MPAD; i += blockDim.x) {
        int k = i / MPAD, j = i - k * MPAD;
        W3s[i] = (j < MOUT) ? W3l[k * MOUT + j] : 0.0f;
    }
    for (int i = threadIdx.x; i < 64; i += blockDim.x) {
        w1ds[i] = W1[(size_t)layer * 257 * 64 + 256 * 64 + i];
        b1s[i]  = b1[layer * 64 + i];
        b2s[i]  = b2[layer * 64 + i];
    }
    for (int i = threadIdx.x; i < MPAD; i += blockDim.x)
        b3s[i] = (i < MOUT) ? b3[layer * MOUT + i] : 0.0f;
    __syncthreads();

    const unsigned FULL = 0xffffffffu;
    const int* dst = ei;
    const int* src = ei + EE;
    int lane = threadIdx.x & 31;
    int gw = (blockIdx.x * blockDim.x + threadIdx.x) >> 5;
    int nw = (gridDim.x * blockDim.x) >> 5;
    const int ngroups = EE / 4;

    for (int g = gw; g < ngroups; g += nw) {
        int base = g * 4;
        int de[4], se[4];
        float Ce[4], dd[4];
#pragma unroll
        for (int e = 0; e < 4; e++) {
            de[e] = dst[base + e]; se[e] = src[base + e];
            Ce[e] = g_C[base + e]; dd[e] = dv[base + e];
        }
        // ---- h1 from pre-projections ----
        float h1a[4], h1b[4];
#pragma unroll
        for (int e = 0; e < 4; e++) {
            const float* Pd = g_P + (size_t)de[e] * 128;
            const float* Ps = g_P + (size_t)se[e] * 128 + 64;
            float pa = Pd[lane]      + Ps[lane]      + dd[e] * w1ds[lane]      + b1s[lane];
            float pb = Pd[lane + 32] + Ps[lane + 32] + dd[e] * w1ds[lane + 32] + b1s[lane + 32];
            h1a[e] = silu(pa); h1b[e] = silu(pb);
        }
        // ---- layer 2: h2 = silu(h1 @ W2 + b2) ----
        float aca[4] = {0.f, 0.f, 0.f, 0.f}, acb[4] = {0.f, 0.f, 0.f, 0.f};
#pragma unroll 4
        for (int k = 0; k < 32; k++) {
            float wa = W2s[k * 64 + lane], wb = W2s[k * 64 + lane + 32];
#pragma unroll
            for (int e = 0; e < 4; e++) {
                float vv = __shfl_sync(FULL, h1a[e], k);
                aca[e] = fmaf(vv, wa, aca[e]); acb[e] = fmaf(vv, wb, acb[e]);
            }
        }
#pragma unroll 4
        for (int k = 0; k < 32; k++) {
            float wa = W2s[(k + 32) * 64 + lane], wb = W2s[(k + 32) * 64 + lane + 32];
#pragma unroll
            for (int e = 0; e < 4; e++) {
                float vv = __shfl_sync(FULL, h1b[e], k);
                aca[e] = fmaf(vv, wa, aca[e]); acb[e] = fmaf(vv, wb, acb[e]);
            }
        }
        float h2a[4], h2b[4];
#pragma unroll
        for (int e = 0; e < 4; e++) {
            h2a[e] = silu(aca[e] + b2s[lane]);
            h2b[e] = silu(acb[e] + b2s[lane + 32]);
        }
        // ---- layer 3: m = h2 @ W3 + b3 (cols j=lane+32c, c<4; c=4 -> col 128+lane) ----
        float acc[4][5];
#pragma unroll
        for (int e = 0; e < 4; e++)
#pragma unroll
            for (int c = 0; c < 5; c++) acc[e][c] = 0.f;
#pragma unroll 4
        for (int k = 0; k < 32; k++) {
            float w0 = W3s[k * MPAD + lane], w1 = W3s[k * MPAD + lane + 32];
            float w2 = W3s[k * MPAD + lane + 64], w3 = W3s[k * MPAD + lane + 96];
            float w4 = W3s[k * MPAD + 128 + lane];
#pragma unroll
            for (int e = 0; e < 4; e++) {
                float vv = __shfl_sync(FULL, h2a[e], k);
                acc[e][0] = fmaf(vv, w0, acc[e][0]); acc[e][1] = fmaf(vv, w1, acc[e][1]);
                acc[e][2] = fmaf(vv, w2, acc[e][2]); acc[e][3] = fmaf(vv, w3, acc[e][3]);
                acc[e][4] = fmaf(vv, w4, acc[e][4]);
            }
        }
#pragma unroll 4
        for (int k = 0; k < 32; k++) {
            float w0 = W3s[(k + 32) * MPAD + lane], w1 = W3s[(k + 32) * MPAD + lane + 32];
            float w2 = W3s[(k + 32) * MPAD + lane + 64], w3 = W3s[(k + 32) * MPAD + lane + 96];
            float w4 = W3s[(k + 32) * MPAD + 128 + lane];
#pragma unroll
            for (int e = 0; e < 4; e++) {
                float vv = __shfl_sync(FULL, h2b[e], k);
                acc[e][0] = fmaf(vv, w0, acc[e][0]); acc[e][1] = fmaf(vv, w1, acc[e][1]);
                acc[e][2] = fmaf(vv, w2, acc[e][2]); acc[e][3] = fmaf(vv, w3, acc[e][3]);
                acc[e][4] = fmaf(vv, w4, acc[e][4]);
            }
        }
        // ---- epilogue: scatter ms and vm ----
        int i3 = lane / 3;   // vm row index for lanes 0..8
#pragma unroll
        for (int e = 0; e < 4; e++) {
            float c0 = Ce[e];
            float* sagg = g_sagg + (size_t)de[e] * 128;
#pragma unroll
            for (int c = 0; c < 4; c++) {
                float val = (acc[e][c] + b3s[lane + 32 * c]) * c0;
                atomicAdd(&sagg[lane + 32 * c], val);
            }
            // gv = m[128..130], gr = m[131..133] (lanes 0..5 hold cols 128+lane)
            float t = acc[e][4] + b3s[128 + lane];
            float gv = __shfl_sync(FULL, t, i3 < 32 ? i3 : 0);
            float gr = __shfl_sync(FULL, t, (i3 + 3) < 32 ? (i3 + 3) : 0);
            if (lane < 9) {
                float vsrc = g_v[(size_t)se[e] * 9 + lane];
                float rvv  = rv[(size_t)(base + e) * 3 + (lane - i3 * 3)];
                float vm = (vsrc * gv + rvv * gr) * c0;
                atomicAdd(&g_vagg[(size_t)de[e] * 9 + lane], vm);
            }
        }
    }
}

// ---------------- node_post: u = silu([s,s_agg]@Wn1+bn1); s += u@Wn2+bn2; v += v_agg*invcnt ----
__global__ __launch_bounds__(256) void k_node_post(
    const float* __restrict__ Wn1, const float* __restrict__ bn1,
    const float* __restrict__ Wn2, const float* __restrict__ bn2, int layer)
{
    extern __shared__ float sm[];
    float* A = sm;                 // 256*64
    float* B = A + 256 * 64;       // 64*128
    float* bb1 = B + 64 * 128;     // 64
    float* bb2 = bb1 + 64;         // 128

    const float* Wn1l = Wn1 + (size_t)layer * 256 * 64;
    const float* Wn2l = Wn2 + (size_t)layer * 64 * 128;
    for (int i = threadIdx.x; i < 256 * 64; i += blockDim.x) A[i] = Wn1l[i];
    for (int i = threadIdx.x; i < 64 * 128; i += blockDim.x) B[i] = Wn2l[i];
    for (int i = threadIdx.x; i < 64; i += blockDim.x)  bb1[i] = bn1[layer * 64 + i];
    for (int i = threadIdx.x; i < 128; i += blockDim.x) bb2[i] = bn2[layer * 128 + i];
    __syncthreads();

    const unsigned FULL = 0xffffffffu;
    int lane = threadIdx.x & 31;
    int gw = (blockIdx.x * blockDim.x + threadIdx.x) >> 5;
    int nw = (gridDim.x * blockDim.x) >> 5;

    for (int n0 = gw * 2; n0 < NN; n0 += nw * 2) {
        int n1 = n0 + 1;
        float4 s0 = ((const float4*)(g_s + (size_t)n0 * 128))[lane];
        float4 s1 = ((const float4*)(g_s + (size_t)n1 * 128))[lane];
        float4 q0 = ((const float4*)(g_sagg + (size_t)n0 * 128))[lane];
        float4 q1 = ((const float4*)(g_sagg + (size_t)n1 * 128))[lane];

        float ua0 = 0.f, ub0 = 0.f, ua1 = 0.f, ub1 = 0.f;
#pragma unroll 8
        for (int k4 = 0; k4 < 32; k4++) {
            float a0[4], a1[4];
            a0[0] = __shfl_sync(FULL, s0.x, k4); a0[1] = __shfl_sync(FULL, s0.y, k4);
            a0[2] = __shfl_sync(FULL, s0.z, k4); a0[3] = __shfl_sync(FULL, s0.w, k4);
            a1[0] = __shfl_sync(FULL, s1.x, k4); a1[1] = __shfl_sync(FULL, s1.y, k4);
            a1[2] = __shfl_sync(FULL, s1.z, k4); a1[3] = __shfl_sync(FULL, s1.w, k4);
#pragma unroll
            for (int c = 0; c < 4; c++) {
                int k = (k4 << 2) + c;
                float wa = A[k * 64 + lane], wb = A[k * 64 + lane + 32];
                ua0 = fmaf(a0[c], wa, ua0); ub0 = fmaf(a0[c], wb, ub0);
                ua1 = fmaf(a1[c], wa, ua1); ub1 = fmaf(a1[c], wb, ub1);
            }
        }
#pragma unroll 8
        for (int k4 = 0; k4 < 32; k4++) {
            float a0[4], a1[4];
            a0[0] = __shfl_sync(FULL, q0.x, k4); a0[1] = __shfl_sync(FULL, q0.y, k4);
            a0[2] = __shfl_sync(FULL, q0.z, k4); a0[3] = __shfl_sync(FULL, q0.w, k4);
            a1[0] = __shfl_sync(FULL, q1.x, k4); a1[1] = __shfl_sync(FULL, q1.y, k4);
            a1[2] = __shfl_sync(FULL, q1.z, k4); a1[3] = __shfl_sync(FULL, q1.w, k4);
#pragma unroll
            for (int c = 0; c < 4; c++) {
                int k = 128 + (k4 << 2) + c;
                float wa = A[k * 64 + lane], wb = A[k * 64 + lane + 32];
                ua0 = fmaf(a0[c], wa, ua0); ub0 = fmaf(a0[c], wb, ub0);
                ua1 = fmaf(a1[c], wa, ua1); ub1 = fmaf(a1[c], wb, ub1);
            }
        }
        float u0a = silu(ua0 + bb1[lane]), u0b = silu(ub0 + bb1[lane + 32]);
        float u1a = silu(ua1 + bb1[lane]), u1b = silu(ub1 + bb1[lane + 32]);

        float4 d0 = make_float4(0.f, 0.f, 0.f, 0.f);
        float4 d1 = make_float4(0.f, 0.f, 0.f, 0.f);
#pragma unroll 4
        for (int k = 0; k < 32; k++) {
            const float4 w = *((const float4*)(B + k * 128 + (lane << 2)));
            float v0 = __shfl_sync(FULL, u0a, k);
            float v1 = __shfl_sync(FULL, u1a, k);
            d0.x = fmaf(v0, w.x, d0.x); d0.y = fmaf(v0, w.y, d0.y);
            d0.z = fmaf(v0, w.z, d0.z); d0.w = fmaf(v0, w.w, d0.w);
            d1.x = fmaf(v1, w.x, d1.x); d1.y = fmaf(v1, w.y, d1.y);
            d1.z = fmaf(v1, w.z, d1.z); d1.w = fmaf(v1, w.w, d1.w);
        }
#pragma unroll 4
        for (int k = 32; k < 64; k++) {
            const float4 w = *((const float4*)(B + k * 128 + (lane << 2)));
            float v0 = __shfl_sync(FULL, u0b, k - 32);
            float v1 = __shfl_sync(FULL, u1b, k - 32);
            d0.x = fmaf(v0, w.x, d0.x); d0.y = fmaf(v0, w.y, d0.y);
            d0.z = fmaf(v0, w.z, d0.z); d0.w = fmaf(v0, w.w, d0.w);
            d1.x = fmaf(v1, w.x, d1.x); d1.y = fmaf(v1, w.y, d1.y);
            d1.z = fmaf(v1, w.z, d1.z); d1.w = fmaf(v1, w.w, d1.w);
        }
        const float4 bbv = *((const float4*)(bb2 + (lane << 2)));
        float4 o0 = make_float4(s0.x + d0.x + bbv.x, s0.y + d0.y + bbv.y,
                                s0.z + d0.z + bbv.z, s0.w + d0.w + bbv.w);
        float4 o1 = make_float4(s1.x + d1.x + bbv.x, s1.y + d1.y + bbv.y,
                                s1.z + d1.z + bbv.z, s1.w + d1.w + bbv.w);
        ((float4*)(g_s + (size_t)n0 * 128))[lane] = o0;
        ((float4*)(g_s + (size_t)n1 * 128))[lane] = o1;
        if (lane < 9) {
            g_v[(size_t)n0 * 9 + lane] += g_vagg[(size_t)n0 * 9 + lane] * g_invcnt[n0];
            g_v[(size_t)n1 * 9 + lane] += g_vagg[(size_t)n1 * 9 + lane] * g_invcnt[n1];
        }
    }
}

// ---------------- output ----------------
__global__ void k_out(float* __restrict__ out)
{
    int idx = blockIdx.x * blockDim.x + threadIdx.x;
    const int ns = NN * SDIM;
    const int total = ns + NN * 9;
    if (idx < ns) out[idx] = g_s[idx];
    else if (idx < total) out[idx] = g_v[idx - ns];
}

// ---------------- launch ----------------
extern "C" void kernel_launch(void* const* d_in, const int* in_sizes, int n_in,
                              void* d_out, int out_size)
{
    const float* s   = (const float*)d_in[0];
    const float* v   = (const float*)d_in[1];
    const int*   ei  = (const int*)d_in[2];
    const float* dv  = (const float*)d_in[3];
    const float* rv  = (const float*)d_in[4];
    const float* W1  = (const float*)d_in[5];
    const float* b1  = (const float*)d_in[6];
    const float* W2  = (const float*)d_in[7];
    const float* b2  = (const float*)d_in[8];
    const float* W3  = (const float*)d_in[9];
    const float* b3  = (const float*)d_in[10];
    const float* Wn1 = (const float*)d_in[11];
    const float* bn1 = (const float*)d_in[12];
    const float* Wn2 = (const float*)d_in[13];
    const float* bn2 = (const float*)d_in[14];
    float* out = (float*)d_out;

    const int SM_PRE  = 128 * 128 * 4;                                     // 65536
    const int SM_EDGE = (64 * 64 + 64 * MPAD + 64 * 3 + MPAD) * 4;         // 58752
    const int SM_POST = (256 * 64 + 64 * 128 + 64 + 128) * 4;              // 99072

    cudaFuncSetAttribute(k_node_pre,  cudaFuncAttributeMaxDynamicSharedMemorySize, SM_PRE);
    cudaFuncSetAttribute(k_edge,      cudaFuncAttributeMaxDynamicSharedMemorySize, SM_EDGE);
    cudaFuncSetAttribute(k_node_post, cudaFuncAttributeMaxDynamicSharedMemorySize, SM_POST);

    k_init<<<(NN * SDIM + 255) / 256, 256>>>(s, v);
    k_edge_init<<<(EE + 255) / 256, 256>>>(ei, dv);
    k_invcnt<<<(NN + 255) / 256, 256>>>();

    for (int l = 0; l < DEPTH; l++) {
        k_node_pre<<<444, 256, SM_PRE>>>(W1, l);
        k_edge<<<592, 256, SM_EDGE>>>(ei, dv, rv, W1, b1, W2, b2, W3, b3, l);
        k_node_post<<<296, 256, SM_POST>>>(Wn1, bn1, Wn2, bn2, l);
    }

    k_out<<<(NN * SDIM + NN * 9 + 255) / 256, 256>>>(out);
}

// round 4
// speedup vs baseline: 1.2129x; 1.2129x over previous
#include <cuda_runtime.h>
#include <math_constants.h>

#define NN 50000
#define EE 500000
#define SDIM 128
#define HID 64
#define DEPTH 4
#define FCUT 5.0f
#define MOUT 134            // SD + 2*VD

// ---------------- scratch (static device arrays, allowed) ----------------
__device__ float g_s[NN * SDIM];
__device__ float g_v[NN * 9];
__device__ float g_P[NN * 128];      // [n][0:64]=s@W1a (dst part), [64:128]=s@W1b (src part)
__device__ float g_H2C[NN * 64];     // sum over incoming edges of C*h2
__device__ float g_vagg[NN * 9];
__device__ float g_C[EE];
__device__ float g_cnt[NN];
__device__ float g_invcnt[NN];
__device__ float g_Csum[NN];
__device__ float g_Wc[DEPTH * 64 * 64];  // W3s @ Wn1_bot per layer
__device__ float g_bc[DEPTH * 64];       // b3s @ Wn1_bot per layer

__device__ __forceinline__ float silu(float x) { return x / (1.0f + __expf(-x)); }

// ---------------- init kernels ----------------
__global__ void k_init(const float* __restrict__ s, const float* __restrict__ v)
{
    int idx = blockIdx.x * blockDim.x + threadIdx.x;
    if (idx < NN * SDIM) g_s[idx] = s[idx];
    if (idx < NN * 9)    g_v[idx] = v[idx];
    if (idx < NN)        { g_cnt[idx] = 0.0f; g_Csum[idx] = 0.0f; }
}

__global__ void k_edge_init(const int* __restrict__ ei, const float* __restrict__ dv)
{
    int e = blockIdx.x * blockDim.x + threadIdx.x;
    if (e >= EE) return;
    float dd = dv[e];
    float c = (dd < FCUT) ? 0.5f * (cosf(CUDART_PI_F * dd / FCUT) + 1.0f) : 0.0f;
    g_C[e] = c;
    int d0 = ei[e];               // row 0 = dst
    atomicAdd(&g_cnt[d0], 1.0f);
    atomicAdd(&g_Csum[d0], c);
}

__global__ void k_invcnt()
{
    int n = blockIdx.x * blockDim.x + threadIdx.x;
    if (n < NN) g_invcnt[n] = 1.0f / fmaxf(g_cnt[n], 1.0f);
}

// ---------------- Wc = W3[:, :128] @ Wn1[128:, :], bc = b3[:128] @ Wn1[128:, :] ----------------
__global__ void k_wc(const float* __restrict__ W3, const float* __restrict__ b3,
                     const float* __restrict__ Wn1)
{
    int l = blockIdx.x;
    const float* W3l  = W3 + (size_t)l * 64 * MOUT;            // [64][134]
    const float* Wn1b = Wn1 + (size_t)l * 256 * 64 + 128 * 64; // [128][64]
    const float* b3l  = b3 + (size_t)l * MOUT;
    for (int idx = threadIdx.x; idx < 64 * 64; idx += blockDim.x) {
        int j = idx >> 6, h = idx & 63;
        float acc = 0.0f;
        for (int c = 0; c < 128; c++)
            acc = fmaf(W3l[j * MOUT + c], Wn1b[c * 64 + h], acc);
        g_Wc[l * 4096 + j * 64 + h] = acc;
    }
    for (int h = threadIdx.x; h < 64; h += blockDim.x) {
        float acc = 0.0f;
        for (int c = 0; c < 128; c++)
            acc = fmaf(b3l[c], Wn1b[c * 64 + h], acc);
        g_bc[l * 64 + h] = acc;
    }
}

// ---------------- node_pre: P = [s@W1a , s@W1b]; zero accumulators (4 nodes/warp) ----------------
__global__ __launch_bounds__(256) void k_node_pre(const float* __restrict__ W1, int layer)
{
    extern __shared__ float sm[];     // 128 x 128 combined weight block (64 KB)
    const float* W1l = W1 + (size_t)layer * 257 * 64;
    for (int i = threadIdx.x; i < 128 * 128; i += blockDim.x) {
        int k = i >> 7, j = i & 127;
        sm[i] = (j < 64) ? W1l[k * 64 + j] : W1l[(128 + k) * 64 + (j - 64)];
    }
    __syncthreads();

    const unsigned FULL = 0xffffffffu;
    int lane = threadIdx.x & 31;
    int gw = (blockIdx.x * blockDim.x + threadIdx.x) >> 5;
    int nw = (gridDim.x * blockDim.x) >> 5;

    for (int n0 = gw * 4; n0 < NN; n0 += nw * 4) {
        float4 sIn[4], acc[4];
#pragma unroll
        for (int t = 0; t < 4; t++) {
            sIn[t] = ((const float4*)(g_s + (size_t)(n0 + t) * SDIM))[lane];
            acc[t] = make_float4(0.f, 0.f, 0.f, 0.f);
        }
#pragma unroll 4
        for (int k4 = 0; k4 < 32; k4++) {
            float a[4][4];
#pragma unroll
            for (int t = 0; t < 4; t++) {
                a[t][0] = __shfl_sync(FULL, sIn[t].x, k4);
                a[t][1] = __shfl_sync(FULL, sIn[t].y, k4);
                a[t][2] = __shfl_sync(FULL, sIn[t].z, k4);
                a[t][3] = __shfl_sync(FULL, sIn[t].w, k4);
            }
#pragma unroll
            for (int c = 0; c < 4; c++) {
                const float4 w = *((const float4*)(sm + (((k4 << 2) + c) << 7) + (lane << 2)));
#pragma unroll
                for (int t = 0; t < 4; t++) {
                    acc[t].x = fmaf(a[t][c], w.x, acc[t].x);
                    acc[t].y = fmaf(a[t][c], w.y, acc[t].y);
                    acc[t].z = fmaf(a[t][c], w.z, acc[t].z);
                    acc[t].w = fmaf(a[t][c], w.w, acc[t].w);
                }
            }
        }
#pragma unroll
        for (int t = 0; t < 4; t++) {
            int n = n0 + t;
            ((float4*)(g_P + (size_t)n * 128))[lane] = acc[t];
            g_H2C[(size_t)n * 64 + lane] = 0.0f;
            g_H2C[(size_t)n * 64 + lane + 32] = 0.0f;
            if (lane < 9) g_vagg[n * 9 + lane] = 0.0f;
        }
    }
}

// ---------------- edge kernel: h1(from P) -> h2; scatter C*h2 into H2C; gv/gr -> vm ----------------
__global__ __launch_bounds__(256) void k_edge(
    const int* __restrict__ ei, const float* __restrict__ dv, const float* __restrict__ rv,
    const float* __restrict__ W1, const float* __restrict__ b1,
    const float* __restrict__ W2, const float* __restrict__ b2,
    const float* __restrict__ W3, const float* __restrict__ b3, int layer)
{
    extern __shared__ float sm[];
    float* W2s  = sm;                  // 64*64
    float* W3vs = W2s + 64 * 64;       // 64*6  (last 6 cols of W3)
    float* w1ds = W3vs + 64 * 6;       // 64
    float* b1s  = w1ds + 64;           // 64
    float* b2s  = b1s + 64;            // 64
    float* b3vs = b2s + 64;            // 6

    const float* W2l = W2 + (size_t)layer * 64 * 64;
    const float* W3l = W3 + (size_t)layer * 64 * MOUT;
    for (int i = threadIdx.x; i < 64 * 64; i += blockDim.x) W2s[i] = W2l[i];
    for (int i = threadIdx.x; i < 64 * 6; i += blockDim.x) {
        int k = i / 6, j = i - 6 * k;
        W3vs[i] = W3l[k * MOUT + 128 + j];
    }
    for (int i = threadIdx.x; i < 64; i += blockDim.x) {
        w1ds[i] = W1[(size_t)layer * 257 * 64 + 256 * 64 + i];
        b1s[i]  = b1[layer * 64 + i];
        b2s[i]  = b2[layer * 64 + i];
    }
    if (threadIdx.x < 6) b3vs[threadIdx.x] = b3[layer * MOUT + 128 + threadIdx.x];
    __syncthreads();

    const unsigned FULL = 0xffffffffu;
    const int* dst = ei;
    const int* src = ei + EE;
    int lane = threadIdx.x & 31;
    int gw = (blockIdx.x * blockDim.x + threadIdx.x) >> 5;
    int nw = (gridDim.x * blockDim.x) >> 5;
    const int ngroups = EE / 4;

    // hoisted per-lane constants
    float w1a = w1ds[lane], w1b = w1ds[lane + 32];
    float b1a = b1s[lane],  b1b = b1s[lane + 32];
    float b2a = b2s[lane],  b2b = b2s[lane + 32];
    float wva[6], wvb[6], bv[6];
#pragma unroll
    for (int j = 0; j < 6; j++) {
        wva[j] = W3vs[lane * 6 + j];
        wvb[j] = W3vs[(lane + 32) * 6 + j];
        bv[j]  = b3vs[j];
    }
    int i3 = lane / 3;
    int x3 = lane - i3 * 3;

    for (int g = gw; g < ngroups; g += nw) {
        int base = g * 4;
        int de[4], se[4];
        float Ce[4], dd[4];
#pragma unroll
        for (int e = 0; e < 4; e++) {
            de[e] = dst[base + e]; se[e] = src[base + e];
            Ce[e] = g_C[base + e]; dd[e] = dv[base + e];
        }
        // ---- h1 from pre-projections ----
        float h1a[4], h1b[4];
#pragma unroll
        for (int e = 0; e < 4; e++) {
            const float* Pd = g_P + (size_t)de[e] * 128;
            const float* Ps = g_P + (size_t)se[e] * 128 + 64;
            float pa = Pd[lane]      + Ps[lane]      + dd[e] * w1a + b1a;
            float pb = Pd[lane + 32] + Ps[lane + 32] + dd[e] * w1b + b1b;
            h1a[e] = silu(pa); h1b[e] = silu(pb);
        }
        // ---- layer 2: h2 = silu(h1 @ W2 + b2) ----
        float aca[4] = {0.f, 0.f, 0.f, 0.f}, acb[4] = {0.f, 0.f, 0.f, 0.f};
#pragma unroll 4
        for (int k = 0; k < 32; k++) {
            float wa = W2s[k * 64 + lane], wb = W2s[k * 64 + lane + 32];
#pragma unroll
            for (int e = 0; e < 4; e++) {
                float vv = __shfl_sync(FULL, h1a[e], k);
                aca[e] = fmaf(vv, wa, aca[e]); acb[e] = fmaf(vv, wb, acb[e]);
            }
        }
#pragma unroll 4
        for (int k = 0; k < 32; k++) {
            float wa = W2s[(k + 32) * 64 + lane], wb = W2s[(k + 32) * 64 + lane + 32];
#pragma unroll
            for (int e = 0; e < 4; e++) {
                float vv = __shfl_sync(FULL, h1b[e], k);
                aca[e] = fmaf(vv, wa, aca[e]); acb[e] = fmaf(vv, wb, acb[e]);
            }
        }
        float h2a[4], h2b[4];
#pragma unroll
        for (int e = 0; e < 4; e++) {
            h2a[e] = silu(aca[e] + b2a);
            h2b[e] = silu(acb[e] + b2b);
        }
        // ---- scatter C*h2 into H2C (64-dim, replaces the 128-col GEMM) ----
#pragma unroll
        for (int e = 0; e < 4; e++) {
            float c0 = Ce[e];
            float* h2c = g_H2C + (size_t)de[e] * 64;
            atomicAdd(&h2c[lane],      c0 * h2a[e]);
            atomicAdd(&h2c[lane + 32], c0 * h2b[e]);
        }
        // ---- gv/gr (6 cols of W3) via butterfly reduction; vm scatter ----
#pragma unroll
        for (int p = 0; p < 2; p++) {
            float acc[12];
#pragma unroll
            for (int e2 = 0; e2 < 2; e2++) {
                int e = p * 2 + e2;
#pragma unroll
                for (int j = 0; j < 6; j++)
                    acc[e2 * 6 + j] = fmaf(h2a[e], wva[j], h2b[e] * wvb[j]);
            }
#pragma unroll
            for (int off = 16; off > 0; off >>= 1) {
#pragma unroll
                for (int i = 0; i < 12; i++)
                    acc[i] += __shfl_xor_sync(FULL, acc[i], off);
            }
#pragma unroll
            for (int e2 = 0; e2 < 2; e2++) {
                int e = p * 2 + e2;
                float s0 = acc[e2 * 6 + 0] + bv[0];
                float s1 = acc[e2 * 6 + 1] + bv[1];
                float s2 = acc[e2 * 6 + 2] + bv[2];
                float s3 = acc[e2 * 6 + 3] + bv[3];
                float s4 = acc[e2 * 6 + 4] + bv[4];
                float s5 = acc[e2 * 6 + 5] + bv[5];
                if (lane < 9) {
                    float gvv = (i3 == 0) ? s0 : (i3 == 1) ? s1 : s2;
                    float grr = (i3 == 0) ? s3 : (i3 == 1) ? s4 : s5;
                    float vsrc = g_v[(size_t)se[e] * 9 + lane];
                    float rvv  = rv[(size_t)(base + e) * 3 + x3];
                    float vm = (vsrc * gvv + rvv * grr) * Ce[e];
                    atomicAdd(&g_vagg[(size_t)de[e] * 9 + lane], vm);
                }
            }
        }
    }
}

// ---------------- node_post: u = silu(s@Wn1_top + H2C@Wc + Csum*bc + bn1); s += u@Wn2+bn2 ----
__global__ __launch_bounds__(256) void k_node_post(
    const float* __restrict__ Wn1, const float* __restrict__ bn1,
    const float* __restrict__ Wn2, const float* __restrict__ bn2, int layer)
{
    extern __shared__ float sm[];
    float* A   = sm;                 // 128*64 (Wn1_top)
    float* Wcs = A + 128 * 64;       // 64*64
    float* B   = Wcs + 64 * 64;      // 64*128 (Wn2)
    float* bb1 = B + 64 * 128;       // 64
    float* bcs = bb1 + 64;           // 64
    float* bb2 = bcs + 64;           // 128

    const float* Wn1l = Wn1 + (size_t)layer * 256 * 64;
    const float* Wn2l = Wn2 + (size_t)layer * 64 * 128;
    for (int i = threadIdx.x; i < 128 * 64; i += blockDim.x) A[i] = Wn1l[i];
    for (int i = threadIdx.x; i < 64 * 64; i += blockDim.x)  Wcs[i] = g_Wc[layer * 4096 + i];
    for (int i = threadIdx.x; i < 64 * 128; i += blockDim.x) B[i] = Wn2l[i];
    for (int i = threadIdx.x; i < 64; i += blockDim.x) {
        bb1[i] = bn1[layer * 64 + i];
        bcs[i] = g_bc[layer * 64 + i];
    }
    for (int i = threadIdx.x; i < 128; i += blockDim.x) bb2[i] = bn2[layer * 128 + i];
    __syncthreads();

    const unsigned FULL = 0xffffffffu;
    int lane = threadIdx.x & 31;
    int gw = (blockIdx.x * blockDim.x + threadIdx.x) >> 5;
    int nw = (gridDim.x * blockDim.x) >> 5;

    float bb1a = bb1[lane], bb1b = bb1[lane + 32];
    float bca = bcs[lane],  bcb = bcs[lane + 32];

    for (int n0 = gw * 2; n0 < NN; n0 += nw * 2) {
        int n1 = n0 + 1;
        float4 s0 = ((const float4*)(g_s + (size_t)n0 * 128))[lane];
        float4 s1 = ((const float4*)(g_s + (size_t)n1 * 128))[lane];
        float h2c0a = g_H2C[(size_t)n0 * 64 + lane];
        float h2c0b = g_H2C[(size_t)n0 * 64 + lane + 32];
        float h2c1a = g_H2C[(size_t)n1 * 64 + lane];
        float h2c1b = g_H2C[(size_t)n1 * 64 + lane + 32];
        float cs0 = g_Csum[n0], cs1 = g_Csum[n1];

        float ua0 = 0.f, ub0 = 0.f, ua1 = 0.f, ub1 = 0.f;
        // ---- s @ Wn1_top (k = 0..127) ----
#pragma unroll 8
        for (int k4 = 0; k4 < 32; k4++) {
            float a0[4], a1[4];
            a0[0] = __shfl_sync(FULL, s0.x, k4); a0[1] = __shfl_sync(FULL, s0.y, k4);
            a0[2] = __shfl_sync(FULL, s0.z, k4); a0[3] = __shfl_sync(FULL, s0.w, k4);
            a1[0] = __shfl_sync(FULL, s1.x, k4); a1[1] = __shfl_sync(FULL, s1.y, k4);
            a1[2] = __shfl_sync(FULL, s1.z, k4); a1[3] = __shfl_sync(FULL, s1.w, k4);
#pragma unroll
            for (int c = 0; c < 4; c++) {
                int k = (k4 << 2) + c;
                float wa = A[k * 64 + lane], wb = A[k * 64 + lane + 32];
                ua0 = fmaf(a0[c], wa, ua0); ub0 = fmaf(a0[c], wb, ub0);
                ua1 = fmaf(a1[c], wa, ua1); ub1 = fmaf(a1[c], wb, ub1);
            }
        }
        // ---- H2C @ Wc (k = 0..63) ----
#pragma unroll 8
        for (int k = 0; k < 32; k++) {
            float wa = Wcs[k * 64 + lane], wb = Wcs[k * 64 + lane + 32];
            float v0 = __shfl_sync(FULL, h2c0a, k);
            float v1 = __shfl_sync(FULL, h2c1a, k);
            ua0 = fmaf(v0, wa, ua0); ub0 = fmaf(v0, wb, ub0);
            ua1 = fmaf(v1, wa, ua1); ub1 = fmaf(v1, wb, ub1);
        }
#pragma unroll 8
        for (int k = 0; k < 32; k++) {
            float wa = Wcs[(k + 32) * 64 + lane], wb = Wcs[(k + 32) * 64 + lane + 32];
            float v0 = __shfl_sync(FULL, h2c0b, k);
            float v1 = __shfl_sync(FULL, h2c1b, k);
            ua0 = fmaf(v0, wa, ua0); ub0 = fmaf(v0, wb, ub0);
            ua1 = fmaf(v1, wa, ua1); ub1 = fmaf(v1, wb, ub1);
        }
        float u0a = silu(ua0 + bb1a + cs0 * bca), u0b = silu(ub0 + bb1b + cs0 * bcb);
        float u1a = silu(ua1 + bb1a + cs1 * bca), u1b = silu(ub1 + bb1b + cs1 * bcb);

        // ---- u @ Wn2 + residual ----
        float4 d0 = make_float4(0.f, 0.f, 0.f, 0.f);
        float4 d1 = make_float4(0.f, 0.f, 0.f, 0.f);
#pragma unroll 4
        for (int k = 0; k < 32; k++) {
            const float4 w = *((const float4*)(B + k * 128 + (lane << 2)));
            float v0 = __shfl_sync(FULL, u0a, k);
            float v1 = __shfl_sync(FULL, u1a, k);
            d0.x = fmaf(v0, w.x, d0.x); d0.y = fmaf(v0, w.y, d0.y);
            d0.z = fmaf(v0, w.z, d0.z); d0.w = fmaf(v0, w.w, d0.w);
            d1.x = fmaf(v1, w.x, d1.x); d1.y = fmaf(v1, w.y, d1.y);
            d1.z = fmaf(v1, w.z, d1.z); d1.w = fmaf(v1, w.w, d1.w);
        }
#pragma unroll 4
        for (int k = 32; k < 64; k++) {
            const float4 w = *((const float4*)(B + k * 128 + (lane << 2)));
            float v0 = __shfl_sync(FULL, u0b, k - 32);
            float v1 = __shfl_sync(FULL, u1b, k - 32);
            d0.x = fmaf(v0, w.x, d0.x); d0.y = fmaf(v0, w.y, d0.y);
            d0.z = fmaf(v0, w.z, d0.z); d0.w = fmaf(v0, w.w, d0.w);
            d1.x = fmaf(v1, w.x, d1.x); d1.y = fmaf(v1, w.y, d1.y);
            d1.z = fmaf(v1, w.z, d1.z); d1.w = fmaf(v1, w.w, d1.w);
        }
        const float4 bbv = *((const float4*)(bb2 + (lane << 2)));
        float4 o0 = make_float4(s0.x + d0.x + bbv.x, s0.y + d0.y + bbv.y,
                                s0.z + d0.z + bbv.z, s0.w + d0.w + bbv.w);
        float4 o1 = make_float4(s1.x + d1.x + bbv.x, s1.y + d1.y + bbv.y,
                                s1.z + d1.z + bbv.z, s1.w + d1.w + bbv.w);
        ((float4*)(g_s + (size_t)n0 * 128))[lane] = o0;
        ((float4*)(g_s + (size_t)n1 * 128))[lane] = o1;
        if (lane < 9) {
            g_v[(size_t)n0 * 9 + lane] += g_vagg[(size_t)n0 * 9 + lane] * g_invcnt[n0];
            g_v[(size_t)n1 * 9 + lane] += g_vagg[(size_t)n1 * 9 + lane] * g_invcnt[n1];
        }
    }
}

// ---------------- output ----------------
__global__ void k_out(float* __restrict__ out)
{
    int idx = blockIdx.x * blockDim.x + threadIdx.x;
    const int ns = NN * SDIM;
    const int total = ns + NN * 9;
    if (idx < ns) out[idx] = g_s[idx];
    else if (idx < total) out[idx] = g_v[idx - ns];
}

// ---------------- launch ----------------
extern "C" void kernel_launch(void* const* d_in, const int* in_sizes, int n_in,
                              void* d_out, int out_size)
{
    const float* s   = (const float*)d_in[0];
    const float* v   = (const float*)d_in[1];
    const int*   ei  = (const int*)d_in[2];
    const float* dv  = (const float*)d_in[3];
    const float* rv  = (const float*)d_in[4];
    const float* W1  = (const float*)d_in[5];
    const float* b1  = (const float*)d_in[6];
    const float* W2  = (const float*)d_in[7];
    const float* b2  = (const float*)d_in[8];
    const float* W3  = (const float*)d_in[9];
    const float* b3  = (const float*)d_in[10];
    const float* Wn1 = (const float*)d_in[11];
    const float* bn1 = (const float*)d_in[12];
    const float* Wn2 = (const float*)d_in[13];
    const float* bn2 = (const float*)d_in[14];
    float* out = (float*)d_out;

    const int SM_PRE  = 128 * 128 * 4;                                    // 65536
    const int SM_EDGE = (64 * 64 + 64 * 6 + 64 * 3 + 6) * 4;              // ~18.7KB
    const int SM_POST = (128 * 64 + 64 * 64 + 64 * 128 + 64 + 64 + 128) * 4; // ~83KB

    cudaFuncSetAttribute(k_node_pre,  cudaFuncAttributeMaxDynamicSharedMemorySize, SM_PRE);
    cudaFuncSetAttribute(k_edge,      cudaFuncAttributeMaxDynamicSharedMemorySize, SM_EDGE);
    cudaFuncSetAttribute(k_node_post, cudaFuncAttributeMaxDynamicSharedMemorySize, SM_POST);

    k_init<<<(NN * SDIM + 255) / 256, 256>>>(s, v);
    k_edge_init<<<(EE + 255) / 256, 256>>>(ei, dv);
    k_invcnt<<<(NN + 255) / 256, 256>>>();
    k_wc<<<DEPTH, 256>>>(W3, b3, Wn1);

    for (int l = 0; l < DEPTH; l++) {
        k_node_pre<<<444, 256, SM_PRE>>>(W1, l);
        k_edge<<<592, 256, SM_EDGE>>>(ei, dv, rv, W1, b1, W2, b2, W3, b3, l);
        k_node_post<<<296, 256, SM_POST>>>(Wn1, bn1, Wn2, bn2, l);
    }

    k_out<<<(NN * SDIM + NN * 9 + 255) / 256, 256>>>(out);
}